// round 10
// baseline (speedup 1.0000x reference)
#include <cuda_runtime.h>
#include <cstdint>

// SeqMasking: right-aligned stable compaction per batch row.
// x:   (B=64, T=2048, D=256) fp32
// rand:(B, T) fp32 ; keep = rand > 0.15
// out[b, T-l+rank(t)] = x[b, t] for kept t; zeros elsewhere.

#define B_ 64
#define T_ 2048
#define D_ 256
#define P_ 0.15f

// Scratch: source-index table, src[b*T + j] = source token t, or -1 (emit zeros).
__device__ int g_src[B_ * T_];

// ---------------------------------------------------------------------------
// Phase 1: one block per batch row. 1024 threads, 2 tokens each.
// Block-wide exclusive scan of keep flags -> ranks; build inverse map g_src.
// ---------------------------------------------------------------------------
__global__ __launch_bounds__(1024) void build_src_kernel(const float* __restrict__ rnd)
{
    const int b    = blockIdx.x;
    const int tid  = threadIdx.x;          // 0..1023
    const int lane = tid & 31;
    const int warp = tid >> 5;             // 0..31

    // Two consecutive tokens per thread.
    const float2 r = reinterpret_cast<const float2*>(rnd + (size_t)b * T_)[tid];
    const int k0 = (r.x > P_) ? 1 : 0;
    const int k1 = (r.y > P_) ? 1 : 0;
    const int pair = k0 + k1;

    // Warp-level inclusive scan of pair counts.
    int incl = pair;
    #pragma unroll
    for (int o = 1; o < 32; o <<= 1) {
        int v = __shfl_up_sync(0xffffffffu, incl, o);
        if (lane >= o) incl += v;
    }

    __shared__ int s_warpTot[32];
    __shared__ int s_warpOff[32];
    __shared__ int s_total;
    if (lane == 31) s_warpTot[warp] = incl;
    __syncthreads();

    if (warp == 0) {
        int v  = s_warpTot[lane];
        int iv = v;
        #pragma unroll
        for (int o = 1; o < 32; o <<= 1) {
            int u = __shfl_up_sync(0xffffffffu, iv, o);
            if (lane >= o) iv += u;
        }
        s_warpOff[lane] = iv - v;          // exclusive warp offset
        if (lane == 31) s_total = iv;      // l = kept count in row
    }
    __syncthreads();

    const int excl = s_warpOff[warp] + (incl - pair); // rank of token 2*tid among kept
    const int l    = s_total;
    const int base = T_ - l;

    // Fill row with -1 (all threads, int2 each: same bytes, no idle warps).
    int* srow = g_src + (size_t)b * T_;
    reinterpret_cast<int2*>(srow)[tid] = make_int2(-1, -1);
    __syncthreads();

    const int t0 = 2 * tid;
    if (k0) srow[base + excl]      = t0;
    if (k1) srow[base + excl + k0] = t0 + 1;
}

// ---------------------------------------------------------------------------
// Phase 2: output-stationary gather. 256 threads/block, 4 tokens/block,
// 64 threads x float4 per token (256 floats = 1KB, fully coalesced).
// ---------------------------------------------------------------------------
__global__ __launch_bounds__(256) void gather_kernel(const float4* __restrict__ x4,
                                                     float4* __restrict__ out4)
{
    const int tok  = blockIdx.x * 4 + (threadIdx.x >> 6);   // global output token (b*T + j)
    const int lane = threadIdx.x & 63;                       // float4 lane within token

    const int s = __ldg(&g_src[tok]);                        // src token in row, or -1
    const int b = tok >> 11;                                 // tok / 2048

    float4 v = make_float4(0.f, 0.f, 0.f, 0.f);
    if (s >= 0) {
        v = __ldg(&x4[((size_t)(b << 11) + s) * (D_ / 4) + lane]);
    }
    out4[(size_t)tok * (D_ / 4) + lane] = v;
}

// ---------------------------------------------------------------------------
extern "C" void kernel_launch(void* const* d_in, const int* in_sizes, int n_in,
                              void* d_out, int out_size)
{
    // Robust input binding: x is the (B,T,D) buffer, rand the (B,T) buffer.
    // Metadata order should be [x, rand]; select by size as insurance.
    const float* x   = (const float*)d_in[0];
    const float* rnd = (const float*)d_in[1];
    if (n_in >= 2 && in_sizes[0] < in_sizes[1]) {
        x   = (const float*)d_in[1];
        rnd = (const float*)d_in[0];
    }
    float* out = (float*)d_out;

    build_src_kernel<<<B_, 1024>>>(rnd);

    const int tokens = B_ * T_;                  // 131072
    gather_kernel<<<tokens / 4, 256>>>((const float4*)x, (float4*)out);

    (void)out_size;
}

// round 14
// speedup vs baseline: 1.1558x; 1.1558x over previous
#include <cuda_runtime.h>
#include <cstdint>

// SeqMasking: right-aligned stable compaction per batch row.
// x:   (B=64, T=2048, D=256) fp32
// rand:(B, T) fp32 ; keep = rand > 0.15
// out[b, T-l+rank(t)] = x[b, t] for kept t; zeros elsewhere.

#define B_ 64
#define T_ 2048
#define D_ 256
#define P_ 0.15f

// Scratch: source-index table, src[b*T + j] = source token t, or -1 (emit zeros).
__device__ int g_src[B_ * T_];

// ---------------------------------------------------------------------------
// Phase 1: one block per batch row. 1024 threads, 2 tokens each.
// Ballot-based rank computation: warp w owns tokens [64w, 64w+64).
// lane handles tokens 64w+lane and 64w+32+lane.
// ---------------------------------------------------------------------------
__global__ __launch_bounds__(1024) void build_src_kernel(const float* __restrict__ rnd)
{
    const int b    = blockIdx.x;
    const int tid  = threadIdx.x;          // 0..1023
    const int lane = tid & 31;
    const int warp = tid >> 5;             // 0..31

    const float* rrow = rnd + (size_t)b * T_;
    const int tA = warp * 64 + lane;        // first token of this lane
    const int tB = tA + 32;                 // second token

    const int kA = (rrow[tA] > P_) ? 1 : 0;
    const int kB = (rrow[tB] > P_) ? 1 : 0;

    const unsigned b0 = __ballot_sync(0xffffffffu, kA);
    const unsigned b1 = __ballot_sync(0xffffffffu, kB);
    const unsigned ltmask = (1u << lane) - 1u;

    __shared__ int s_warpTot[32];
    __shared__ int s_warpOff[32];
    __shared__ int s_total;
    if (lane == 0) s_warpTot[warp] = __popc(b0) + __popc(b1);
    __syncthreads();

    if (warp == 0) {
        int v  = s_warpTot[lane];
        int iv = v;
        #pragma unroll
        for (int o = 1; o < 32; o <<= 1) {
            int u = __shfl_up_sync(0xffffffffu, iv, o);
            if (lane >= o) iv += u;
        }
        s_warpOff[lane] = iv - v;          // exclusive warp offset
        if (lane == 31) s_total = iv;      // l = kept count in row
    }
    __syncthreads();

    const int woff  = s_warpOff[warp];
    const int rankA = woff + __popc(b0 & ltmask);
    const int rankB = woff + __popc(b0) + __popc(b1 & ltmask);
    const int base  = T_ - s_total;

    // Fill row with -1 (all threads, int2 each), then scatter kept src indices.
    int* srow = g_src + (size_t)b * T_;
    reinterpret_cast<int2*>(srow)[tid] = make_int2(-1, -1);
    __syncthreads();

    if (kA) srow[base + rankA] = tA;
    if (kB) srow[base + rankB] = tB;
}

// ---------------------------------------------------------------------------
// Phase 2: output-stationary gather, MLP=4.
// 256 threads/block = 4 groups of 64 threads; each group handles 4 consecutive
// output tokens (src indices fetched as one int4). Per thread: 4 independent
// LDG.128 in flight, then 4 coalesced STG.128. 16 tokens/block, grid 8192.
// ---------------------------------------------------------------------------
__global__ __launch_bounds__(256) void gather_kernel(const float4* __restrict__ x4,
                                                     float4* __restrict__ out4)
{
    const int grp     = threadIdx.x >> 6;                    // 0..3
    const int lane    = threadIdx.x & 63;                    // float4 lane within token
    const int tokBase = blockIdx.x * 16 + grp * 4;           // 4-aligned; same row (4 | 2048)

    const int4 s4 = *reinterpret_cast<const int4*>(&g_src[tokBase]);
    const int  b  = tokBase >> 11;                           // row
    const float4* xrow = x4 + ((size_t)b << 11) * (D_ / 4);  // row base

    float4 v0 = make_float4(0.f, 0.f, 0.f, 0.f);
    float4 v1 = v0, v2 = v0, v3 = v0;
    if (s4.x >= 0) v0 = __ldg(&xrow[(size_t)s4.x * (D_ / 4) + lane]);
    if (s4.y >= 0) v1 = __ldg(&xrow[(size_t)s4.y * (D_ / 4) + lane]);
    if (s4.z >= 0) v2 = __ldg(&xrow[(size_t)s4.z * (D_ / 4) + lane]);
    if (s4.w >= 0) v3 = __ldg(&xrow[(size_t)s4.w * (D_ / 4) + lane]);

    float4* orow = out4 + (size_t)tokBase * (D_ / 4) + lane;
    orow[0 * (D_ / 4)] = v0;
    orow[1 * (D_ / 4)] = v1;
    orow[2 * (D_ / 4)] = v2;
    orow[3 * (D_ / 4)] = v3;
}

// ---------------------------------------------------------------------------
extern "C" void kernel_launch(void* const* d_in, const int* in_sizes, int n_in,
                              void* d_out, int out_size)
{
    // Robust input binding: x is the (B,T,D) buffer, rand the (B,T) buffer.
    const float* x   = (const float*)d_in[0];
    const float* rnd = (const float*)d_in[1];
    if (n_in >= 2 && in_sizes[0] < in_sizes[1]) {
        x   = (const float*)d_in[1];
        rnd = (const float*)d_in[0];
    }
    float* out = (float*)d_out;

    build_src_kernel<<<B_, 1024>>>(rnd);

    const int tokens = B_ * T_;                  // 131072
    gather_kernel<<<tokens / 16, 256>>>((const float4*)x, (float4*)out);

    (void)out_size;
}